// round 1
// baseline (speedup 1.0000x reference)
#include <cuda_runtime.h>
#include <math.h>

#define HH   256
#define WW   256
#define CCH  32
#define NB   16
#define TAPS 49
#define TO   64   // output tile
#define TD   70   // dilation tile (TO + 6)
#define TU   76   // convected-u tile (TO + 12)
#define SUS  80   // smem stride for u tile
#define SDS  72   // smem stride for dil tile

// Scratch for erosion output (before channel mix): 134 MB, module-global (allowed).
__device__ float g_scratch[(size_t)NB * CCH * HH * WW];
__device__ float g_kd[CCH][TAPS];
__device__ float g_ke[CCH][TAPS];
__device__ int   g_ixy[CCH][2];
__device__ float g_bw[CCH][4];

// ---------------------------------------------------------------------------
// Setup: morphological kernel tables + per-channel bilinear shift params.
// ---------------------------------------------------------------------------
__global__ void setup_kernel(const float* __restrict__ cc,
                             const float* __restrict__ fd,
                             const float* __restrict__ fe) {
    int ch  = blockIdx.x;
    int tap = threadIdx.x;
    if (tap < TAPS) {
        float fdy = (float)(tap / 7 - 3);
        float fdx = (float)(tap % 7 - 3);
        float rho = sqrtf(fdx * fdx + fdy * fdy);
        float th  = atan2f(fdy, fdx);
        float b0 = cosf(th), b1 = sinf(th);
        float b2 = cosf(2.0f * th), b3 = sinf(2.0f * th);
        const float P  = 2.0f * 0.65f / (2.0f * 0.65f - 1.0f);   // 13/3
        const float NU = (2.0f * 0.65f - 1.0f) * powf(2.0f * 0.65f, -P);
        float s1 = fd[ch*4+0]*b0 + fd[ch*4+1]*b1 + fd[ch*4+2]*b2 + fd[ch*4+3]*b3;
        g_kd[ch][tap] = NU * powf(rho * expf(-s1), P);
        float s2 = fe[ch*4+0]*b0 + fe[ch*4+1]*b1 + fe[ch*4+2]*b2 + fe[ch*4+3]*b3;
        g_ke[ch][tap] = NU * powf(rho * expf(-s2), P);
    } else if (tap == TAPS) {
        // convection: u(x) = x_in(x - c). For integer pixel p: g = p - s,
        // floor(g) = p + floor(-s); frac is constant per channel.
        float sx = cc[ch*2+0], sy = cc[ch*2+1];
        float fy = -sy, fx = -sx;
        float iy = floorf(fy), ix = floorf(fx);
        float wy = fy - iy,    wx = fx - ix;
        g_ixy[ch][0] = (int)iy;
        g_ixy[ch][1] = (int)ix;
        g_bw[ch][0] = (1.0f - wy) * (1.0f - wx);
        g_bw[ch][1] = (1.0f - wy) * wx;
        g_bw[ch][2] = wy * (1.0f - wx);
        g_bw[ch][3] = wy * wx;
    }
}

// ---------------------------------------------------------------------------
// Fused convection + dilation + erosion over one (b, ch, 64x64) tile.
// dilation = max_taps(u - kd)  (out-of-image u := -BIG)
// erosion  = min_taps(d + ke)  (out-of-image d := +BIG)
// ---------------------------------------------------------------------------
__global__ __launch_bounds__(256) void morph_kernel(const float* __restrict__ x) {
    __shared__ float su[TU][SUS];
    __shared__ float sd[TD][SDS];
    __shared__ float skd[TAPS];
    __shared__ float ske[TAPS];

    int tid = threadIdx.x;
    int ch  = blockIdx.z & (CCH - 1);
    int b   = blockIdx.z >> 5;
    int Y0  = blockIdx.y * TO;
    int X0  = blockIdx.x * TO;

    if (tid < TAPS) { skd[tid] = g_kd[ch][tid]; ske[tid] = g_ke[ch][tid]; }
    int   iy  = g_ixy[ch][0], ix = g_ixy[ch][1];
    float w00 = g_bw[ch][0], w01 = g_bw[ch][1];
    float w10 = g_bw[ch][2], w11 = g_bw[ch][3];
    const float* __restrict__ plane = x + (size_t)(b * CCH + ch) * HH * WW;

    // Phase 1: convected u with 6-wide halo (bilinear, replicate boundary).
    for (int idx = tid; idx < TU * TU; idx += 256) {
        int ly = idx / TU, lx = idx - ly * TU;
        int gy = Y0 - 6 + ly, gx = X0 - 6 + lx;
        float v = -1e30f;
        if ((unsigned)gy < HH && (unsigned)gx < WW) {
            int y0 = min(max(gy + iy, 0), HH - 1);
            int y1 = min(y0 + 1, HH - 1);
            int x0 = min(max(gx + ix, 0), WW - 1);
            int x1 = min(x0 + 1, WW - 1);
            const float* r0 = plane + y0 * WW;
            const float* r1 = plane + y1 * WW;
            v = w00 * r0[x0] + w01 * r0[x1] + w10 * r1[x0] + w11 * r1[x1];
        }
        su[ly][lx] = v;
    }
    __syncthreads();

    // Phase 2: dilation on 70x70 grid, 4-wide microtile with sliding window.
    for (int item = tid; item < TD * 18; item += 256) {
        int ly = item / 18;
        int lx = (item - ly * 18) * 4;
        float m0 = -1e30f, m1 = -1e30f, m2 = -1e30f, m3 = -1e30f;
        #pragma unroll
        for (int oy = 0; oy < 7; oy++) {
            const float* row = &su[ly + oy][lx];
            float v[10];
            #pragma unroll
            for (int t = 0; t < 10; t++) v[t] = row[t];
            #pragma unroll
            for (int ox = 0; ox < 7; ox++) {
                float k = skd[oy * 7 + ox];
                m0 = fmaxf(m0, v[ox + 0] - k);
                m1 = fmaxf(m1, v[ox + 1] - k);
                m2 = fmaxf(m2, v[ox + 2] - k);
                m3 = fmaxf(m3, v[ox + 3] - k);
            }
        }
        int gy = Y0 - 3 + ly;
        int gx = X0 - 3 + lx;
        bool iny = (unsigned)gy < HH;
        sd[ly][lx + 0] = (iny && (unsigned)(gx + 0) < WW) ? m0 : 1e30f;
        sd[ly][lx + 1] = (iny && (unsigned)(gx + 1) < WW) ? m1 : 1e30f;
        sd[ly][lx + 2] = (iny && (unsigned)(gx + 2) < WW) ? m2 : 1e30f;
        sd[ly][lx + 3] = (iny && (unsigned)(gx + 3) < WW) ? m3 : 1e30f;
    }
    __syncthreads();

    // Phase 3: erosion on the 64x64 output tile, write to scratch.
    float* __restrict__ wout = g_scratch + (size_t)(b * CCH + ch) * HH * WW;
    for (int item = tid; item < TO * 16; item += 256) {
        int ly = item >> 4;
        int lx = (item & 15) * 4;
        float m0 = 1e30f, m1 = 1e30f, m2 = 1e30f, m3 = 1e30f;
        #pragma unroll
        for (int oy = 0; oy < 7; oy++) {
            const float* row = &sd[ly + oy][lx];
            float v[10];
            #pragma unroll
            for (int t = 0; t < 10; t++) v[t] = row[t];
            #pragma unroll
            for (int ox = 0; ox < 7; ox++) {
                float k = ske[oy * 7 + ox];
                m0 = fminf(m0, v[ox + 0] + k);
                m1 = fminf(m1, v[ox + 1] + k);
                m2 = fminf(m2, v[ox + 2] + k);
                m3 = fminf(m3, v[ox + 3] + k);
            }
        }
        float4 r = make_float4(m0, m1, m2, m3);
        *(float4*)(wout + (size_t)(Y0 + ly) * WW + X0 + lx) = r;
    }
}

// ---------------------------------------------------------------------------
// Channel mix: out[b,o,p] = sum_i w[b,i,p] * W[i,o], packed f32x2 FMA
// (2 pixels per thread, duplicated weights in smem -> 1 LDS.64 + 1 FFMA2
//  per (i,o) per 2 pixels).
// ---------------------------------------------------------------------------
__global__ __launch_bounds__(256) void mix_kernel(const float* __restrict__ wt,
                                                  float* __restrict__ out) {
    __shared__ unsigned long long sW[CCH * CCH];
    int tid = threadIdx.x;
    for (int i = tid; i < CCH * CCH; i += 256) {
        float w = wt[i];
        float2 p = make_float2(w, w);
        sW[i] = *reinterpret_cast<unsigned long long*>(&p);
    }
    __syncthreads();

    int b   = blockIdx.y;
    int pix = blockIdx.x * 512 + tid * 2;
    const float* inp = g_scratch + (size_t)b * CCH * HH * WW + pix;
    float*       op  = out       + (size_t)b * CCH * HH * WW + pix;

    unsigned long long acc[CCH];
    #pragma unroll
    for (int o = 0; o < CCH; o++) acc[o] = 0ull;

    float2 vnext = *reinterpret_cast<const float2*>(inp);
    #pragma unroll 1
    for (int i = 0; i < CCH; i++) {
        float2 vcur = vnext;
        if (i < CCH - 1)
            vnext = *reinterpret_cast<const float2*>(inp + (size_t)(i + 1) * HH * WW);
        unsigned long long v = *reinterpret_cast<unsigned long long*>(&vcur);
        const unsigned long long* wrow = &sW[i * CCH];
        #pragma unroll
        for (int o = 0; o < CCH; o++) {
            asm("fma.rn.f32x2 %0, %1, %2, %0;" : "+l"(acc[o]) : "l"(v), "l"(wrow[o]));
        }
    }
    #pragma unroll 1
    for (int o = 0; o < CCH; o++) {
        *reinterpret_cast<unsigned long long*>(op + (size_t)o * HH * WW) = acc[o];
    }
}

// ---------------------------------------------------------------------------
extern "C" void kernel_launch(void* const* d_in, const int* in_sizes, int n_in,
                              void* d_out, int out_size) {
    const float* x  = (const float*)d_in[0];
    const float* c  = (const float*)d_in[1];
    const float* fd = (const float*)d_in[2];
    const float* fe = (const float*)d_in[3];
    const float* wt = (const float*)d_in[4];
    float* out = (float*)d_out;

    setup_kernel<<<CCH, 64>>>(c, fd, fe);

    dim3 g1(WW / TO, HH / TO, NB * CCH);   // (4, 4, 512)
    morph_kernel<<<g1, 256>>>(x);

    dim3 g2((HH * WW) / 512, NB);          // (128, 16)
    mix_kernel<<<g2, 256>>>(wt, out);
}

// round 2
// speedup vs baseline: 1.2217x; 1.2217x over previous
#include <cuda_runtime.h>
#include <math.h>

#define HH   256
#define WW   256
#define CCH  32
#define NB   16
#define TAPS 49
#define TO   64          // output tile (64x64)
#define SUS  84          // su stride in floats (21 float4, odd -> bank spread)
#define SDS  76          // sd stride in floats (19 float4, odd -> bank spread)
// su: rows 0..77 (78), valid cols 0..79 (80)   -> covers dil-grid reads
// sd: rows 0..71 (72), valid cols 0..71 (72)   -> covers erosion reads

// Scratch for erosion output (before channel mix): 134 MB, module-global (allowed).
__device__ float g_scratch[(size_t)NB * CCH * HH * WW];
__device__ float g_kd[CCH][TAPS];
__device__ float g_ke[CCH][TAPS];
__device__ int   g_ixy[CCH][2];
__device__ float g_bw[CCH][4];

// ---------------------------------------------------------------------------
// Setup: morphological kernel tables + per-channel bilinear shift params.
// ---------------------------------------------------------------------------
__global__ void setup_kernel(const float* __restrict__ cc,
                             const float* __restrict__ fd,
                             const float* __restrict__ fe) {
    int ch  = blockIdx.x;
    int tap = threadIdx.x;
    if (tap < TAPS) {
        float fdy = (float)(tap / 7 - 3);
        float fdx = (float)(tap % 7 - 3);
        float rho = sqrtf(fdx * fdx + fdy * fdy);
        float th  = atan2f(fdy, fdx);
        float b0 = cosf(th), b1 = sinf(th);
        float b2 = cosf(2.0f * th), b3 = sinf(2.0f * th);
        const float P  = 2.0f * 0.65f / (2.0f * 0.65f - 1.0f);   // 13/3
        const float NU = (2.0f * 0.65f - 1.0f) * powf(2.0f * 0.65f, -P);
        float s1 = fd[ch*4+0]*b0 + fd[ch*4+1]*b1 + fd[ch*4+2]*b2 + fd[ch*4+3]*b3;
        g_kd[ch][tap] = NU * powf(rho * expf(-s1), P);
        float s2 = fe[ch*4+0]*b0 + fe[ch*4+1]*b1 + fe[ch*4+2]*b2 + fe[ch*4+3]*b3;
        g_ke[ch][tap] = NU * powf(rho * expf(-s2), P);
    } else if (tap == TAPS) {
        float sx = cc[ch*2+0], sy = cc[ch*2+1];
        float fy = -sy, fx = -sx;
        float iy = floorf(fy), ix = floorf(fx);
        float wy = fy - iy,    wx = fx - ix;
        g_ixy[ch][0] = (int)iy;
        g_ixy[ch][1] = (int)ix;
        g_bw[ch][0] = (1.0f - wy) * (1.0f - wx);
        g_bw[ch][1] = (1.0f - wy) * wx;
        g_bw[ch][2] = wy * (1.0f - wx);
        g_bw[ch][3] = wy * wx;
    }
}

// ---------------------------------------------------------------------------
// Fused convection + dilation + erosion over one (b, ch, 64x64) tile.
// dilation = max_taps(u - kd)  (out-of-image u := -BIG)
// erosion  = min_taps(d + ke)  (out-of-image d := +BIG)
// 4x4 register microtiles, float4 smem loads, fully unrolled tap loops.
// ---------------------------------------------------------------------------
__global__ __launch_bounds__(256) void morph_kernel(const float* __restrict__ x) {
    __shared__ float su[78 * SUS];
    __shared__ float sd[72 * SDS];
    __shared__ float skd[TAPS];
    __shared__ float ske[TAPS];

    int tid = threadIdx.x;
    int ch  = blockIdx.z & (CCH - 1);
    int b   = blockIdx.z >> 5;
    int Y0  = blockIdx.y * TO;
    int X0  = blockIdx.x * TO;

    if (tid < TAPS) { skd[tid] = g_kd[ch][tid]; ske[tid] = g_ke[ch][tid]; }
    int   iy  = g_ixy[ch][0], ix = g_ixy[ch][1];
    float w00 = g_bw[ch][0], w01 = g_bw[ch][1];
    float w10 = g_bw[ch][2], w11 = g_bw[ch][3];
    const float* __restrict__ plane = x + (size_t)(b * CCH + ch) * HH * WW;

    // Phase 1: convected u, 78 rows x 80 cols (origin at tile - (6,6)).
    for (int idx = tid; idx < 78 * 80; idx += 256) {
        int ly = idx / 80, lx = idx - ly * 80;
        int gy = Y0 - 6 + ly, gx = X0 - 6 + lx;
        float v = -1e30f;
        if ((unsigned)gy < HH && (unsigned)gx < WW) {
            int y0 = min(max(gy + iy, 0), HH - 1);
            int y1 = min(y0 + 1, HH - 1);
            int x0 = min(max(gx + ix, 0), WW - 1);
            int x1 = min(x0 + 1, WW - 1);
            const float* r0 = plane + y0 * WW;
            const float* r1 = plane + y1 * WW;
            v = w00 * r0[x0] + w01 * r0[x1] + w10 * r1[x0] + w11 * r1[x1];
        }
        su[ly * SUS + lx] = v;
    }
    __syncthreads();

    // Phase 2: dilation on 72x72 grid (70x70 valid), 4x4 microtiles (18x18 items).
    for (int item = tid; item < 18 * 18; item += 256) {
        int miy = item / 18;
        int mix = item - miy * 18;
        int r0  = miy * 4;          // sd row base
        int c0  = mix * 4;          // col base (floats)

        float a[4][4];
        #pragma unroll
        for (int r = 0; r < 4; r++)
            #pragma unroll
            for (int cx = 0; cx < 4; cx++) a[r][cx] = -1e30f;

        #pragma unroll
        for (int wy = 0; wy < 10; wy++) {
            const float4* rp = (const float4*)&su[(r0 + wy) * SUS + c0];
            float4 q0 = rp[0], q1 = rp[1], q2 = rp[2];
            float v[12] = {q0.x, q0.y, q0.z, q0.w, q1.x, q1.y, q1.z, q1.w,
                           q2.x, q2.y, q2.z, q2.w};
            #pragma unroll
            for (int dy = 0; dy < 7; dy++) {
                int r = wy - dy;
                if (r < 0 || r > 3) continue;      // compile-time pruned
                #pragma unroll
                for (int ox = 0; ox < 7; ox++) {
                    float k = skd[dy * 7 + ox];
                    #pragma unroll
                    for (int cx = 0; cx < 4; cx++)
                        a[r][cx] = fmaxf(a[r][cx], v[ox + cx] - k);
                }
            }
        }

        #pragma unroll
        for (int r = 0; r < 4; r++) {
            int gy = Y0 - 3 + r0 + r;
            int gx = X0 - 3 + c0;
            bool iny = (unsigned)gy < HH;
            float4 s;
            s.x = (iny && (unsigned)(gx + 0) < WW) ? a[r][0] : 1e30f;
            s.y = (iny && (unsigned)(gx + 1) < WW) ? a[r][1] : 1e30f;
            s.z = (iny && (unsigned)(gx + 2) < WW) ? a[r][2] : 1e30f;
            s.w = (iny && (unsigned)(gx + 3) < WW) ? a[r][3] : 1e30f;
            *(float4*)&sd[(r0 + r) * SDS + c0] = s;
        }
    }
    __syncthreads();

    // Phase 3: erosion on 64x64 output tile, 4x4 microtile, exactly 1 item/thread.
    {
        int miy = tid >> 4;
        int mix = tid & 15;
        int r0  = miy * 4;
        int c0  = mix * 4;

        float a[4][4];
        #pragma unroll
        for (int r = 0; r < 4; r++)
            #pragma unroll
            for (int cx = 0; cx < 4; cx++) a[r][cx] = 1e30f;

        #pragma unroll
        for (int wy = 0; wy < 10; wy++) {
            const float4* rp = (const float4*)&sd[(r0 + wy) * SDS + c0];
            float4 q0 = rp[0], q1 = rp[1], q2 = rp[2];
            float v[12] = {q0.x, q0.y, q0.z, q0.w, q1.x, q1.y, q1.z, q1.w,
                           q2.x, q2.y, q2.z, q2.w};
            #pragma unroll
            for (int dy = 0; dy < 7; dy++) {
                int r = wy - dy;
                if (r < 0 || r > 3) continue;
                #pragma unroll
                for (int ox = 0; ox < 7; ox++) {
                    float k = ske[dy * 7 + ox];
                    #pragma unroll
                    for (int cx = 0; cx < 4; cx++)
                        a[r][cx] = fminf(a[r][cx], v[ox + cx] + k);
                }
            }
        }

        float* __restrict__ wout = g_scratch + (size_t)(b * CCH + ch) * HH * WW;
        #pragma unroll
        for (int r = 0; r < 4; r++) {
            float4 s = make_float4(a[r][0], a[r][1], a[r][2], a[r][3]);
            *(float4*)(wout + (size_t)(Y0 + r0 + r) * WW + X0 + c0) = s;
        }
    }
}

// ---------------------------------------------------------------------------
// Channel mix: out[b,o,p] = sum_i w[b,i,p] * W[i,o], packed f32x2 FMA.
// ---------------------------------------------------------------------------
__global__ __launch_bounds__(256) void mix_kernel(const float* __restrict__ wt,
                                                  float* __restrict__ out) {
    __shared__ unsigned long long sW[CCH * CCH];
    int tid = threadIdx.x;
    for (int i = tid; i < CCH * CCH; i += 256) {
        float w = wt[i];
        float2 p = make_float2(w, w);
        sW[i] = *reinterpret_cast<unsigned long long*>(&p);
    }
    __syncthreads();

    int b   = blockIdx.y;
    int pix = blockIdx.x * 512 + tid * 2;
    const float* inp = g_scratch + (size_t)b * CCH * HH * WW + pix;
    float*       op  = out       + (size_t)b * CCH * HH * WW + pix;

    unsigned long long acc[CCH];
    #pragma unroll
    for (int o = 0; o < CCH; o++) acc[o] = 0ull;

    float2 vnext = *reinterpret_cast<const float2*>(inp);
    #pragma unroll 1
    for (int i = 0; i < CCH; i++) {
        float2 vcur = vnext;
        if (i < CCH - 1)
            vnext = *reinterpret_cast<const float2*>(inp + (size_t)(i + 1) * HH * WW);
        unsigned long long v = *reinterpret_cast<unsigned long long*>(&vcur);
        const unsigned long long* wrow = &sW[i * CCH];
        #pragma unroll
        for (int o = 0; o < CCH; o++) {
            asm("fma.rn.f32x2 %0, %1, %2, %0;" : "+l"(acc[o]) : "l"(v), "l"(wrow[o]));
        }
    }
    #pragma unroll 1
    for (int o = 0; o < CCH; o++) {
        *reinterpret_cast<unsigned long long*>(op + (size_t)o * HH * WW) = acc[o];
    }
}

// ---------------------------------------------------------------------------
extern "C" void kernel_launch(void* const* d_in, const int* in_sizes, int n_in,
                              void* d_out, int out_size) {
    const float* x  = (const float*)d_in[0];
    const float* c  = (const float*)d_in[1];
    const float* fd = (const float*)d_in[2];
    const float* fe = (const float*)d_in[3];
    const float* wt = (const float*)d_in[4];
    float* out = (float*)d_out;

    setup_kernel<<<CCH, 64>>>(c, fd, fe);

    dim3 g1(WW / TO, HH / TO, NB * CCH);   // (4, 4, 512)
    morph_kernel<<<g1, 256>>>(x);

    dim3 g2((HH * WW) / 512, NB);          // (128, 16)
    mix_kernel<<<g2, 256>>>(wt, out);
}